// round 15
// baseline (speedup 1.0000x reference)
#include <cuda_runtime.h>
#include <cuda_fp16.h>

#define W      512
#define NIMG   32
#define CH     4
#define NGRP   (NIMG / 8)      // 4 image groups of 8
#define CHUNKS (W / CH)        // 128 angle chunks
#define CHUNK_BYTES 65536      // 4 angles x 2 tabs x 512 entries x 16B
#define NBUF   3

// Scratch: filtered projections transposed to [n][angle][r]
__device__ __align__(16) float g_proj[(size_t)NIMG * W * W];
// Packed fp16 quad tables: [group][angle l][tab][k], 16B entries:
//   tab t entry: {h2(p_a,p_b), h2(d_a,d_b), h2(p_c,p_d), h2(d_c,d_d)}
//   tab 0 -> imgs 0..3, tab 1 -> imgs 4..7 of the group.
__device__ __align__(16) uint4 g_pairs[(size_t)NGRP * W * 2 * 512];
// Ramp-filter spatial taps, rearranged: g_hh[i] = h[(i-511) mod 1024]
__device__ float g_hh[1024];
// Per-angle (cos*255.5, sin*255.5)
__device__ float2 g_cs[W];

// ---------------------------------------------------------------------------
// K0: taps. h[m] = (1/1024) * sum_k filt[k] * cos(2*pi*k*m/1024),
// filt[k] = min(k,1024-k)/512. One block per tap, 256-thread double reduction.
// ---------------------------------------------------------------------------
__global__ __launch_bounds__(256) void k_hh() {
    __shared__ double red[256];
    const int i = blockIdx.x;
    const int t = threadIdx.x;
    if (i == 1023) { if (t == 0) g_hh[1023] = 0.0f; return; }
    const int m2 = (i + 513) & 1023;              // (i-511) mod 1024
    double s = 0.0;
    for (int k = t; k < 1024; k += 256) {
        int mn = (k < 512) ? k : (1024 - k);
        float f = (float)mn * (1.0f / 512.0f);    // filt[k]
        int ph = (k * m2) & 1023;                 // exact integer phase
        s += (double)f * (double)cospif((float)ph * (1.0f / 512.0f));
    }
    red[t] = s;
    __syncthreads();
    for (int st = 128; st > 0; st >>= 1) {
        if (t < st) red[t] += red[t + st];
        __syncthreads();
    }
    if (t == 0) g_hh[i] = (float)(red[0] / 1024.0);
}

__global__ void k_trig(const float* __restrict__ theta) {
    int l = threadIdx.x;
    if (l < W) {
        float frac = theta[l] * (1.0f / 180.0f);
        g_cs[l] = make_float2(cospif(frac) * 255.5f, sinpif(frac) * 255.5f);
    }
}

// ---------------------------------------------------------------------------
// K1: ramp filter as Toeplitz GEMM, output transposed:
//   g_proj[n][l][r] = sum_{m=0}^{511} x[n][m][l] * hh[r - m + 511]
// 256 threads, tile 128 l x 128 r, micro-tile 8l x 8r, packed fma.rn.f32x2.
// ---------------------------------------------------------------------------
__global__ __launch_bounds__(256) void k_filter(const float* __restrict__ x) {
    __shared__ __align__(16) float2 hh2[1023];  // hh2[i] = (hh[i], hh[i+1])
    __shared__ __align__(16) float  As[16][128];
    const int tid = threadIdx.x;
    const int n     = blockIdx.z;
    const int rBase = blockIdx.x * 128;
    const int lBase = blockIdx.y * 128;

    for (int i = tid; i < 1023; i += 256)
        hh2[i] = make_float2(g_hh[i], g_hh[i + 1]);

    const int tx = tid & 15;          // l lane (strided by 16)
    const int ty = tid >> 4;          // r group (8 consecutive r)
    const int r0 = rBase + ty * 8;

    unsigned long long acc[8][4];     // [sl][pair]: pair p = (r0+2p, r0+2p+1)
#pragma unroll
    for (int sl = 0; sl < 8; ++sl)
#pragma unroll
        for (int p = 0; p < 4; ++p) acc[sl][p] = 0ull;

    const float* xn = x + (size_t)n * W * W;
    const int lrow = tid >> 5;        // 0..7
    const int c4   = (tid & 31) << 2; // 0..124

    for (int mc = 0; mc < 32; ++mc) {
        __syncthreads();
        const float* src = xn + (size_t)(mc * 16) * W + lBase;
        *(float4*)&As[lrow][c4]     = *(const float4*)(src + (size_t)lrow * W + c4);
        *(float4*)&As[lrow + 8][c4] = *(const float4*)(src + (size_t)(lrow + 8) * W + c4);
        __syncthreads();
#pragma unroll
        for (int mm = 0; mm < 16; ++mm) {
            const int hb = 511 + r0 - (mc * 16 + mm);
            unsigned long long h2[4];
#pragma unroll
            for (int p = 0; p < 4; ++p)
                h2[p] = *(const unsigned long long*)(&hh2[hb + 2 * p]);
#pragma unroll
            for (int sl = 0; sl < 8; ++sl) {
                float a = As[mm][tx + 16 * sl];
                unsigned long long a2;
                asm("mov.b64 %0, {%1, %1};" : "=l"(a2) : "r"(__float_as_uint(a)));
#pragma unroll
                for (int p = 0; p < 4; ++p)
                    asm("fma.rn.f32x2 %0, %1, %2, %0;"
                        : "+l"(acc[sl][p]) : "l"(a2), "l"(h2[p]));
            }
        }
    }

#pragma unroll
    for (int sl = 0; sl < 8; ++sl) {
        const int l = lBase + tx + 16 * sl;
        float v[8];
#pragma unroll
        for (int p = 0; p < 4; ++p) {
            unsigned int lo, hi;
            asm("mov.b64 {%0, %1}, %2;" : "=r"(lo), "=r"(hi) : "l"(acc[sl][p]));
            v[2 * p]     = __uint_as_float(lo);
            v[2 * p + 1] = __uint_as_float(hi);
        }
        float* dst = g_proj + ((size_t)n * W + l) * W + r0;
        *(float4*)dst       = make_float4(v[0], v[1], v[2], v[3]);
        *(float4*)(dst + 4) = make_float4(v[4], v[5], v[6], v[7]);
    }
}

// pack two fp32 into half2 (lo in low half, hi in high half): 1 instr (F2FP)
__device__ __forceinline__ unsigned pack_f16x2(float lo, float hi) {
    unsigned r;
    asm("cvt.rn.f16x2.f32 %0, %2, %1;" : "=r"(r) : "f"(lo), "f"(hi));
    return r;
}

__device__ __forceinline__ __half2 u2h2(unsigned v) {
    return *reinterpret_cast<__half2*>(&v);
}

// ---------------------------------------------------------------------------
// K1.5: build packed fp16 quad tables from g_proj for 8-image groups.
// Block = one (group g, angle l); thread strides k. Entry (16B) holds
// p/d pairs for 4 images so K2 fetches them with one LDS.128.
// Index: ((g*512 + l)*2 + tab)*512 + k  ->  each (g, 4-angle chunk) is one
// contiguous 64KB block for cp.async.
// ---------------------------------------------------------------------------
__global__ __launch_bounds__(128) void k_pack() {
    const int bid = blockIdx.x;            // g*512 + l
    const int g = bid >> 9;
    const int l = bid & 511;
    const int t = threadIdx.x;
    const float* base = g_proj + ((size_t)g * 8) * W * W + (size_t)l * W;
#pragma unroll
    for (int s = 0; s < 4; ++s) {
        int k  = t + s * 128;
        int kn = (k < W - 1) ? (k + 1) : k;      // k=511 -> d=0
        float p[8], d[8];
#pragma unroll
        for (int m = 0; m < 8; ++m) {
            p[m] = base[k  + (size_t)m * W * W];
            d[m] = base[kn + (size_t)m * W * W] - p[m];
        }
#pragma unroll
        for (int tab = 0; tab < 2; ++tab) {
            int m0 = tab * 4;
            g_pairs[(((size_t)bid * 2) + tab) * 512 + k] =
                make_uint4(pack_f16x2(p[m0 + 0], p[m0 + 1]),
                           pack_f16x2(d[m0 + 0], d[m0 + 1]),
                           pack_f16x2(p[m0 + 2], p[m0 + 3]),
                           pack_f16x2(d[m0 + 2], d[m0 + 3]));
        }
    }
}

// ---------------------------------------------------------------------------
// K2: backprojection, 8 images per block, triple-buffered cp.async pipeline.
// Block = 512 thr = 16 rows x 32 lanes; thread owns 8 pixels
// (j = chh*256 + lane + 32u) of 8 images. All 4 chunk angles are lerped in
// fp16 (LDS.128 quad entry -> 2x HFMA2 per tab per angle), tree-merged with
// HADD2, and flushed to fp32 ONCE per chunk (4 angles) -- flush cost halved
// vs per-pair flushing.
// Index via single 2^23 magic: mantissa of (ry + 2^23) IS floor(ry);
// "& 0x1FF" keeps in-circle values exact (floor in [0,511]) and wraps
// out-of-circle garbage in-bounds (those pixels are masked at the end).
// ---------------------------------------------------------------------------
__global__ __launch_bounds__(512, 1) void k_backproj(float* __restrict__ out) {
    extern __shared__ __align__(16) char sm[];   // NBUF * CHUNK_BYTES
    const int tid  = threadIdx.x;
    const int rg   = blockIdx.x >> 1;       // row group (0..31)
    const int chh  = blockIdx.x & 1;        // column half
    const int n0   = blockIdx.y * 8;
    const int i    = rg * 16 + (tid >> 5);
    const int lane = tid & 31;
    const float STEP = 2.0f / 511.0f;
    const float ti   = fmaf((float)i, STEP, -1.0f);
    const float tj0  = fmaf((float)(chh * 256 + lane), STEP, -1.0f);
    const float UST0 = 32.0f * STEP;

    const char* gp = (const char*)g_pairs + (size_t)blockIdx.y * CHUNKS * CHUNK_BYTES;
    const unsigned smbase = (unsigned)__cvta_generic_to_shared(sm);

    // issue one chunk's 64KB copy: 4096 x 16B, 8 ops/thread
#define ISSUE(lc_)                                                          \
    do {                                                                    \
        const int _lc = (lc_);                                              \
        const unsigned _dst = smbase + (unsigned)(_lc % NBUF) * CHUNK_BYTES; \
        const char* _src = gp + (size_t)_lc * CHUNK_BYTES;                  \
        _Pragma("unroll")                                                   \
        for (int _s = 0; _s < 8; ++_s) {                                    \
            unsigned _o = (unsigned)(tid + _s * 512) * 16u;                 \
            asm volatile("cp.async.cg.shared.global [%0], [%1], 16;"        \
                         :: "r"(_dst + _o), "l"(_src + _o));                \
        }                                                                   \
        asm volatile("cp.async.commit_group;");                             \
    } while (0)

    ISSUE(0);
    ISSUE(1);

    float acc[8][8];                         // [image][u]
#pragma unroll
    for (int m = 0; m < 8; ++m)
#pragma unroll
        for (int u = 0; u < 8; ++u) acc[m][u] = 0.0f;

    for (int lc = 0; lc < CHUNKS; ++lc) {
        if (lc < CHUNKS - 2) asm volatile("cp.async.wait_group 1;");
        else                 asm volatile("cp.async.wait_group 0;");
        __syncthreads();
        // Early prefetch of lc+2: buffer (lc+2)%3 == (lc-1)%3, and the
        // barrier above proves every warp finished reading chunk lc-1.
        if (lc + 2 < CHUNKS) ISSUE(lc + 2);

        const char* cbase = sm + (lc % NBUF) * CHUNK_BYTES;
        const float4 csA = *(const float4*)&g_cs[lc * CH];      // c0,s0,c1,s1
        const float4 csB = *(const float4*)&g_cs[lc * CH + 2];  // c2,s2,c3,s3
        const float cA[4] = {csA.x, csA.z, csB.x, csB.z};
        const float sA[4] = {csA.y, csA.w, csB.y, csB.w};
        float ry0[4], ust[4];
#pragma unroll
        for (int a = 0; a < 4; ++a) {
            ry0[a] = fmaf(tj0, cA[a], fmaf(-ti, sA[a], 255.5f));
            ust[a] = cA[a] * UST0;
        }

#pragma unroll
        for (int u = 0; u < 8; ++u) {
            unsigned off[4];
            __half2  hf[4];
#pragma unroll
            for (int a = 0; a < 4; ++a) {
                float ry = fmaf((float)u, ust[a], ry0[a]);
                float b;
                asm("add.rm.f32 %0, %1, 0f4B000000;" : "=f"(b) : "f"(ry));
                off[a] = (__float_as_uint(b) & 0x1FFu) * 16u;
                float frac = ry - (b - 8388608.0f);
                hf[a] = u2h2(pack_f16x2(frac, frac));
            }
            // tab 0: images 0..3
            uint4 e0 = *(const uint4*)(cbase + 0 * 16384 + off[0]);
            uint4 e1 = *(const uint4*)(cbase + 1 * 16384 + off[1]);
            uint4 e2 = *(const uint4*)(cbase + 2 * 16384 + off[2]);
            uint4 e3 = *(const uint4*)(cbase + 3 * 16384 + off[3]);
            __half2 w0 = __hadd2(
                __hadd2(__hfma2(hf[0], u2h2(e0.y), u2h2(e0.x)),
                        __hfma2(hf[1], u2h2(e1.y), u2h2(e1.x))),
                __hadd2(__hfma2(hf[2], u2h2(e2.y), u2h2(e2.x)),
                        __hfma2(hf[3], u2h2(e3.y), u2h2(e3.x))));
            __half2 w1 = __hadd2(
                __hadd2(__hfma2(hf[0], u2h2(e0.w), u2h2(e0.z)),
                        __hfma2(hf[1], u2h2(e1.w), u2h2(e1.z))),
                __hadd2(__hfma2(hf[2], u2h2(e2.w), u2h2(e2.z)),
                        __hfma2(hf[3], u2h2(e3.w), u2h2(e3.z))));
            // tab 1: images 4..7
            uint4 f0 = *(const uint4*)(cbase + 0 * 16384 + 8192 + off[0]);
            uint4 f1 = *(const uint4*)(cbase + 1 * 16384 + 8192 + off[1]);
            uint4 f2 = *(const uint4*)(cbase + 2 * 16384 + 8192 + off[2]);
            uint4 f3 = *(const uint4*)(cbase + 3 * 16384 + 8192 + off[3]);
            __half2 w2 = __hadd2(
                __hadd2(__hfma2(hf[0], u2h2(f0.y), u2h2(f0.x)),
                        __hfma2(hf[1], u2h2(f1.y), u2h2(f1.x))),
                __hadd2(__hfma2(hf[2], u2h2(f2.y), u2h2(f2.x)),
                        __hfma2(hf[3], u2h2(f3.y), u2h2(f3.x))));
            __half2 w3 = __hadd2(
                __hadd2(__hfma2(hf[0], u2h2(f0.w), u2h2(f0.z)),
                        __hfma2(hf[1], u2h2(f1.w), u2h2(f1.z))),
                __hadd2(__hfma2(hf[2], u2h2(f2.w), u2h2(f2.z)),
                        __hfma2(hf[3], u2h2(f3.w), u2h2(f3.z))));
            // fp32 flush once per chunk
            acc[0][u] += __low2float(w0);  acc[1][u] += __high2float(w0);
            acc[2][u] += __low2float(w1);  acc[3][u] += __high2float(w1);
            acc[4][u] += __low2float(w2);  acc[5][u] += __high2float(w2);
            acc[6][u] += __low2float(w3);  acc[7][u] += __high2float(w3);
        }
    }
#undef ISSUE

    const float scale = (float)(3.14159265358979323846 / 1024.0); // pi/(2L)
    const float ti2 = ti * ti;
#pragma unroll
    for (int u = 0; u < 8; ++u) {
        int j = chh * 256 + lane + 32 * u;
        float tj = fmaf((float)j, STEP, -1.0f);
        bool in = (ti2 + tj * tj <= 1.0f);
        float* po = out + ((size_t)n0 * W + i) * W + j;
#pragma unroll
        for (int m = 0; m < 8; ++m)
            po[(size_t)m * W * W] = in ? acc[m][u] * scale : 0.0f;
    }
}

extern "C" void kernel_launch(void* const* d_in, const int* in_sizes, int n_in,
                              void* d_out, int out_size) {
    const float* x     = (const float*)d_in[0];
    const float* theta = (const float*)d_in[1];
    if (n_in >= 2 && in_sizes[0] == W && in_sizes[1] != W) { // defensive order swap
        x = (const float*)d_in[1];
        theta = (const float*)d_in[0];
    }
    float* out = (float*)d_out;

    const int smbytes = NBUF * CHUNK_BYTES;   // 192 KB dynamic smem
    cudaFuncSetAttribute(k_backproj, cudaFuncAttributeMaxDynamicSharedMemorySize,
                         smbytes);

    k_hh<<<1024, 256>>>();
    k_trig<<<1, 512>>>(theta);

    dim3 g1(4, 4, NIMG);
    k_filter<<<g1, 256>>>(x);

    k_pack<<<NGRP * W, 128>>>();

    dim3 g2(64, NGRP);
    k_backproj<<<g2, 512, smbytes>>>(out);
}

// round 16
// speedup vs baseline: 1.0079x; 1.0079x over previous
#include <cuda_runtime.h>
#include <cuda_fp16.h>

#define W      512
#define NIMG   32
#define CH     4
#define NGRP   (NIMG / 8)      // 4 image groups of 8
#define CHUNKS (W / CH)        // 128 angle chunks
#define CHUNK_BYTES 65536      // 4 angles x 2 tabs x 512 entries x 16B
#define NBUF   3

// Scratch: filtered projections transposed to [n][angle][r]
__device__ __align__(16) float g_proj[(size_t)NIMG * W * W];
// Packed fp16 quad tables: [group][angle l][tab][k], 16B entries:
//   tab t entry: {h2(p_a,p_b), h2(d_a,d_b), h2(p_c,p_d), h2(d_c,d_d)}
//   tab 0 -> imgs 0..3, tab 1 -> imgs 4..7 of the group.
__device__ __align__(16) uint4 g_pairs[(size_t)NGRP * W * 2 * 512];
// Ramp-filter spatial taps, rearranged: g_hh[i] = h[(i-511) mod 1024]
__device__ float g_hh[1024];
// Per-angle (cos*255.5, sin*255.5)
__device__ float2 g_cs[W];

// ---------------------------------------------------------------------------
// K0: taps. h[m] = (1/1024) * sum_k filt[k] * cos(2*pi*k*m/1024),
// filt[k] = min(k,1024-k)/512. One block per tap, 256-thread double reduction.
// ---------------------------------------------------------------------------
__global__ __launch_bounds__(256) void k_hh() {
    __shared__ double red[256];
    const int i = blockIdx.x;
    const int t = threadIdx.x;
    if (i == 1023) { if (t == 0) g_hh[1023] = 0.0f; return; }
    const int m2 = (i + 513) & 1023;              // (i-511) mod 1024
    double s = 0.0;
    for (int k = t; k < 1024; k += 256) {
        int mn = (k < 512) ? k : (1024 - k);
        float f = (float)mn * (1.0f / 512.0f);    // filt[k]
        int ph = (k * m2) & 1023;                 // exact integer phase
        s += (double)f * (double)cospif((float)ph * (1.0f / 512.0f));
    }
    red[t] = s;
    __syncthreads();
    for (int st = 128; st > 0; st >>= 1) {
        if (t < st) red[t] += red[t + st];
        __syncthreads();
    }
    if (t == 0) g_hh[i] = (float)(red[0] / 1024.0);
}

__global__ void k_trig(const float* __restrict__ theta) {
    int l = threadIdx.x;
    if (l < W) {
        float frac = theta[l] * (1.0f / 180.0f);
        g_cs[l] = make_float2(cospif(frac) * 255.5f, sinpif(frac) * 255.5f);
    }
}

// ---------------------------------------------------------------------------
// K1: ramp filter as Toeplitz GEMM, output transposed:
//   g_proj[n][l][r] = sum_{m=0}^{511} x[n][m][l] * hh[r - m + 511]
// 256 threads, tile 128 l x 128 r, micro-tile 8l x 8r, packed fma.rn.f32x2.
// A-tile staging is double-buffered via cp.async: chunk mc+1 is prefetched
// right after the barrier while chunk mc computes (removes the exposed
// LDG->STS round trip per chunk). Arithmetic identical to the sync version.
// ---------------------------------------------------------------------------
__global__ __launch_bounds__(256) void k_filter(const float* __restrict__ x) {
    __shared__ __align__(16) float2 hh2[1023];  // hh2[i] = (hh[i], hh[i+1])
    __shared__ __align__(16) float  As[2][16][128];
    const int tid = threadIdx.x;
    const int n     = blockIdx.z;
    const int rBase = blockIdx.x * 128;
    const int lBase = blockIdx.y * 128;

    for (int i = tid; i < 1023; i += 256)
        hh2[i] = make_float2(g_hh[i], g_hh[i + 1]);

    const int tx = tid & 15;          // l lane (strided by 16)
    const int ty = tid >> 4;          // r group (8 consecutive r)
    const int r0 = rBase + ty * 8;

    unsigned long long acc[8][4];     // [sl][pair]: pair p = (r0+2p, r0+2p+1)
#pragma unroll
    for (int sl = 0; sl < 8; ++sl)
#pragma unroll
        for (int p = 0; p < 4; ++p) acc[sl][p] = 0ull;

    const float* xn = x + (size_t)n * W * W;
    const int lrow = tid >> 5;        // 0..7
    const int c4   = (tid & 31) << 2; // 0..124
    const unsigned asb = (unsigned)__cvta_generic_to_shared(&As[0][0][0])
                       + (unsigned)(lrow * 128 + c4) * 4u;

    // stage chunk mc's 16x128 A-tile into buffer mc&1 (2 x 16B per thread)
#define ISSUEF(mc_)                                                         \
    do {                                                                    \
        const int _mc = (mc_);                                              \
        const float* _src = xn + (size_t)(_mc * 16) * W + lBase;            \
        unsigned _d = asb + (unsigned)(_mc & 1) * 8192u;                    \
        asm volatile("cp.async.cg.shared.global [%0], [%1], 16;"            \
                     :: "r"(_d), "l"(_src + (size_t)lrow * W + c4));        \
        asm volatile("cp.async.cg.shared.global [%0], [%1], 16;"            \
                     :: "r"(_d + 4096u),                                    \
                        "l"(_src + (size_t)(lrow + 8) * W + c4));           \
        asm volatile("cp.async.commit_group;");                             \
    } while (0)

    ISSUEF(0);

    for (int mc = 0; mc < 32; ++mc) {
        asm volatile("cp.async.wait_group 0;");
        __syncthreads();
        if (mc + 1 < 32) ISSUEF(mc + 1);   // buffer (mc+1)&1: all warps proved
                                           // done with chunk mc-1 by barrier
        const float (*A)[128] = As[mc & 1];
#pragma unroll
        for (int mm = 0; mm < 16; ++mm) {
            const int hb = 511 + r0 - (mc * 16 + mm);
            unsigned long long h2[4];
#pragma unroll
            for (int p = 0; p < 4; ++p)
                h2[p] = *(const unsigned long long*)(&hh2[hb + 2 * p]);
#pragma unroll
            for (int sl = 0; sl < 8; ++sl) {
                float a = A[mm][tx + 16 * sl];
                unsigned long long a2;
                asm("mov.b64 %0, {%1, %1};" : "=l"(a2) : "r"(__float_as_uint(a)));
#pragma unroll
                for (int p = 0; p < 4; ++p)
                    asm("fma.rn.f32x2 %0, %1, %2, %0;"
                        : "+l"(acc[sl][p]) : "l"(a2), "l"(h2[p]));
            }
        }
    }
#undef ISSUEF

#pragma unroll
    for (int sl = 0; sl < 8; ++sl) {
        const int l = lBase + tx + 16 * sl;
        float v[8];
#pragma unroll
        for (int p = 0; p < 4; ++p) {
            unsigned int lo, hi;
            asm("mov.b64 {%0, %1}, %2;" : "=r"(lo), "=r"(hi) : "l"(acc[sl][p]));
            v[2 * p]     = __uint_as_float(lo);
            v[2 * p + 1] = __uint_as_float(hi);
        }
        float* dst = g_proj + ((size_t)n * W + l) * W + r0;
        *(float4*)dst       = make_float4(v[0], v[1], v[2], v[3]);
        *(float4*)(dst + 4) = make_float4(v[4], v[5], v[6], v[7]);
    }
}

// pack two fp32 into half2 (lo in low half, hi in high half): 1 instr (F2FP)
__device__ __forceinline__ unsigned pack_f16x2(float lo, float hi) {
    unsigned r;
    asm("cvt.rn.f16x2.f32 %0, %2, %1;" : "=r"(r) : "f"(lo), "f"(hi));
    return r;
}

__device__ __forceinline__ __half2 u2h2(unsigned v) {
    return *reinterpret_cast<__half2*>(&v);
}

// ---------------------------------------------------------------------------
// K1.5: build packed fp16 quad tables from g_proj for 8-image groups.
// Block = one (group g, angle l); thread strides k. Entry (16B) holds
// p/d pairs for 4 images so K2 fetches them with one LDS.128.
// Index: ((g*512 + l)*2 + tab)*512 + k  ->  each (g, 4-angle chunk) is one
// contiguous 64KB block for cp.async.
// ---------------------------------------------------------------------------
__global__ __launch_bounds__(128) void k_pack() {
    const int bid = blockIdx.x;            // g*512 + l
    const int g = bid >> 9;
    const int l = bid & 511;
    const int t = threadIdx.x;
    const float* base = g_proj + ((size_t)g * 8) * W * W + (size_t)l * W;
#pragma unroll
    for (int s = 0; s < 4; ++s) {
        int k  = t + s * 128;
        int kn = (k < W - 1) ? (k + 1) : k;      // k=511 -> d=0
        float p[8], d[8];
#pragma unroll
        for (int m = 0; m < 8; ++m) {
            p[m] = base[k  + (size_t)m * W * W];
            d[m] = base[kn + (size_t)m * W * W] - p[m];
        }
#pragma unroll
        for (int tab = 0; tab < 2; ++tab) {
            int m0 = tab * 4;
            g_pairs[(((size_t)bid * 2) + tab) * 512 + k] =
                make_uint4(pack_f16x2(p[m0 + 0], p[m0 + 1]),
                           pack_f16x2(d[m0 + 0], d[m0 + 1]),
                           pack_f16x2(p[m0 + 2], p[m0 + 3]),
                           pack_f16x2(d[m0 + 2], d[m0 + 3]));
        }
    }
}

// ---------------------------------------------------------------------------
// K2: backprojection, 8 images per block, triple-buffered cp.async pipeline.
// Block = 512 thr = 16 rows x 32 lanes; thread owns 8 pixels
// (j = chh*256 + lane + 32u) of 8 images. Angles processed in PAIRS:
// each angle's lerp stays fp16 (LDS.128 quad entry -> 2x HFMA2 per tab),
// the pair is merged with HADD2, and converted/accumulated to fp32 once
// per 2 angles (halves the F2F+FADD cost).
// Index via single 2^23 magic: mantissa of (ry + 2^23) IS floor(ry);
// "& 0x1FF" keeps in-circle values exact (floor in [0,511]) and wraps
// out-of-circle garbage in-bounds (those pixels are masked at the end).
// ---------------------------------------------------------------------------
__global__ __launch_bounds__(512, 1) void k_backproj(float* __restrict__ out) {
    extern __shared__ __align__(16) char sm[];   // NBUF * CHUNK_BYTES
    const int tid  = threadIdx.x;
    const int rg   = blockIdx.x >> 1;       // row group (0..31)
    const int chh  = blockIdx.x & 1;        // column half
    const int n0   = blockIdx.y * 8;
    const int i    = rg * 16 + (tid >> 5);
    const int lane = tid & 31;
    const float STEP = 2.0f / 511.0f;
    const float ti   = fmaf((float)i, STEP, -1.0f);
    const float tj0  = fmaf((float)(chh * 256 + lane), STEP, -1.0f);
    const float UST0 = 32.0f * STEP;

    const char* gp = (const char*)g_pairs + (size_t)blockIdx.y * CHUNKS * CHUNK_BYTES;
    const unsigned smbase = (unsigned)__cvta_generic_to_shared(sm);

    // issue one chunk's 64KB copy: 4096 x 16B, 8 ops/thread
#define ISSUE(lc_)                                                          \
    do {                                                                    \
        const int _lc = (lc_);                                              \
        const unsigned _dst = smbase + (unsigned)(_lc % NBUF) * CHUNK_BYTES; \
        const char* _src = gp + (size_t)_lc * CHUNK_BYTES;                  \
        _Pragma("unroll")                                                   \
        for (int _s = 0; _s < 8; ++_s) {                                    \
            unsigned _o = (unsigned)(tid + _s * 512) * 16u;                 \
            asm volatile("cp.async.cg.shared.global [%0], [%1], 16;"        \
                         :: "r"(_dst + _o), "l"(_src + _o));                \
        }                                                                   \
        asm volatile("cp.async.commit_group;");                             \
    } while (0)

    ISSUE(0);
    ISSUE(1);

    float acc[8][8];                         // [image][u]
#pragma unroll
    for (int m = 0; m < 8; ++m)
#pragma unroll
        for (int u = 0; u < 8; ++u) acc[m][u] = 0.0f;

    for (int lc = 0; lc < CHUNKS; ++lc) {
        if (lc < CHUNKS - 2) asm volatile("cp.async.wait_group 1;");
        else                 asm volatile("cp.async.wait_group 0;");
        __syncthreads();
        // Early prefetch of lc+2: buffer (lc+2)%3 == (lc-1)%3, and the
        // barrier above proves every warp finished reading chunk lc-1.
        if (lc + 2 < CHUNKS) ISSUE(lc + 2);

        const char* cbase = sm + (lc % NBUF) * CHUNK_BYTES;
        const float4 csA = *(const float4*)&g_cs[lc * CH];      // c0,s0,c1,s1
        const float4 csB = *(const float4*)&g_cs[lc * CH + 2];  // c2,s2,c3,s3

#pragma unroll
        for (int ap = 0; ap < 2; ++ap) {      // angle pair (2*ap, 2*ap+1)
            const float cE = (ap == 0) ? csA.x : csB.x;
            const float sE = (ap == 0) ? csA.y : csB.y;
            const float cO = (ap == 0) ? csA.z : csB.z;
            const float sO = (ap == 0) ? csA.w : csB.w;
            const float rowE = fmaf(-ti, sE, 255.5f);
            const float rowO = fmaf(-ti, sO, 255.5f);
            const float ry0E = fmaf(tj0, cE, rowE);
            const float ry0O = fmaf(tj0, cO, rowO);
            const float ustE = cE * UST0;
            const float ustO = cO * UST0;
            const char* PE = cbase + (2 * ap)     * 16384;  // tab0; tab1 at +8192
            const char* PO = cbase + (2 * ap + 1) * 16384;
#pragma unroll
            for (int u = 0; u < 8; ++u) {
                // even angle
                float ryE = fmaf((float)u, ustE, ry0E);
                float bE;
                asm("add.rm.f32 %0, %1, 0f4B000000;" : "=f"(bE) : "f"(ryE));
                unsigned offE = (__float_as_uint(bE) & 0x1FFu) * 16u;
                float frE = ryE - (bE - 8388608.0f);
                __half2 hfE = u2h2(pack_f16x2(frE, frE));
                uint4 ea = *(const uint4*)(PE + offE);
                uint4 eb = *(const uint4*)(PE + 8192 + offE);
                __half2 e0 = __hfma2(hfE, u2h2(ea.y), u2h2(ea.x));
                __half2 e1 = __hfma2(hfE, u2h2(ea.w), u2h2(ea.z));
                __half2 e2 = __hfma2(hfE, u2h2(eb.y), u2h2(eb.x));
                __half2 e3 = __hfma2(hfE, u2h2(eb.w), u2h2(eb.z));
                // odd angle
                float ryO = fmaf((float)u, ustO, ry0O);
                float bO;
                asm("add.rm.f32 %0, %1, 0f4B000000;" : "=f"(bO) : "f"(ryO));
                unsigned offO = (__float_as_uint(bO) & 0x1FFu) * 16u;
                float frO = ryO - (bO - 8388608.0f);
                __half2 hfO = u2h2(pack_f16x2(frO, frO));
                uint4 oa = *(const uint4*)(PO + offO);
                uint4 ob = *(const uint4*)(PO + 8192 + offO);
                __half2 m0 = __hadd2(e0, __hfma2(hfO, u2h2(oa.y), u2h2(oa.x)));
                __half2 m1 = __hadd2(e1, __hfma2(hfO, u2h2(oa.w), u2h2(oa.z)));
                __half2 m2 = __hadd2(e2, __hfma2(hfO, u2h2(ob.y), u2h2(ob.x)));
                __half2 m3 = __hadd2(e3, __hfma2(hfO, u2h2(ob.w), u2h2(ob.z)));
                acc[0][u] += __low2float(m0);  acc[1][u] += __high2float(m0);
                acc[2][u] += __low2float(m1);  acc[3][u] += __high2float(m1);
                acc[4][u] += __low2float(m2);  acc[5][u] += __high2float(m2);
                acc[6][u] += __low2float(m3);  acc[7][u] += __high2float(m3);
            }
        }
    }
#undef ISSUE

    const float scale = (float)(3.14159265358979323846 / 1024.0); // pi/(2L)
    const float ti2 = ti * ti;
#pragma unroll
    for (int u = 0; u < 8; ++u) {
        int j = chh * 256 + lane + 32 * u;
        float tj = fmaf((float)j, STEP, -1.0f);
        bool in = (ti2 + tj * tj <= 1.0f);
        float* po = out + ((size_t)n0 * W + i) * W + j;
#pragma unroll
        for (int m = 0; m < 8; ++m)
            po[(size_t)m * W * W] = in ? acc[m][u] * scale : 0.0f;
    }
}

extern "C" void kernel_launch(void* const* d_in, const int* in_sizes, int n_in,
                              void* d_out, int out_size) {
    const float* x     = (const float*)d_in[0];
    const float* theta = (const float*)d_in[1];
    if (n_in >= 2 && in_sizes[0] == W && in_sizes[1] != W) { // defensive order swap
        x = (const float*)d_in[1];
        theta = (const float*)d_in[0];
    }
    float* out = (float*)d_out;

    const int smbytes = NBUF * CHUNK_BYTES;   // 192 KB dynamic smem
    cudaFuncSetAttribute(k_backproj, cudaFuncAttributeMaxDynamicSharedMemorySize,
                         smbytes);

    k_hh<<<1024, 256>>>();
    k_trig<<<1, 512>>>(theta);

    dim3 g1(4, 4, NIMG);
    k_filter<<<g1, 256>>>(x);

    k_pack<<<NGRP * W, 128>>>();

    dim3 g2(64, NGRP);
    k_backproj<<<g2, 512, smbytes>>>(out);
}

// round 17
// speedup vs baseline: 1.0655x; 1.0572x over previous
#include <cuda_runtime.h>
#include <cuda_fp16.h>

#define W      512
#define NIMG   32
#define CH     4
#define NGRP   (NIMG / 8)      // 4 image groups of 8
#define CHUNKS (W / CH)        // 128 angle chunks
#define CHUNK_BYTES 65536      // 4 angles x 2 tabs x 512 entries x 16B
#define NBUF   3

// Scratch: filtered projections transposed to [n][angle][r]
__device__ __align__(16) float g_proj[(size_t)NIMG * W * W];
// Packed fp16 quad tables: [group][angle l][tab][k], 16B entries:
//   tab t entry: {h2(p_a,p_b), h2(d_a,d_b), h2(p_c,p_d), h2(d_c,d_d)}
//   tab 0 -> imgs 0..3, tab 1 -> imgs 4..7 of the group.
__device__ __align__(16) uint4 g_pairs[(size_t)NGRP * W * 2 * 512];
// Ramp-filter spatial taps, rearranged: g_hh[i] = h[(i-511) mod 1024]
__device__ float g_hh[1024];
// Per-angle (cos*255.5, sin*255.5)
__device__ float2 g_cs[W];

// ---------------------------------------------------------------------------
// K0: taps. h[m] = (1/1024) * sum_k filt[k] * cos(2*pi*k*m/1024),
// filt[k] = min(k,1024-k)/512. One block per tap, 256-thread double reduction.
// ---------------------------------------------------------------------------
__global__ __launch_bounds__(256) void k_hh() {
    __shared__ double red[256];
    const int i = blockIdx.x;
    const int t = threadIdx.x;
    if (i == 1023) { if (t == 0) g_hh[1023] = 0.0f; return; }
    const int m2 = (i + 513) & 1023;              // (i-511) mod 1024
    double s = 0.0;
    for (int k = t; k < 1024; k += 256) {
        int mn = (k < 512) ? k : (1024 - k);
        float f = (float)mn * (1.0f / 512.0f);    // filt[k]
        int ph = (k * m2) & 1023;                 // exact integer phase
        s += (double)f * (double)cospif((float)ph * (1.0f / 512.0f));
    }
    red[t] = s;
    __syncthreads();
    for (int st = 128; st > 0; st >>= 1) {
        if (t < st) red[t] += red[t + st];
        __syncthreads();
    }
    if (t == 0) g_hh[i] = (float)(red[0] / 1024.0);
}

__global__ void k_trig(const float* __restrict__ theta) {
    int l = threadIdx.x;
    if (l < W) {
        float frac = theta[l] * (1.0f / 180.0f);
        g_cs[l] = make_float2(cospif(frac) * 255.5f, sinpif(frac) * 255.5f);
    }
}

// ---------------------------------------------------------------------------
// K1: ramp filter as Toeplitz GEMM, output transposed:
//   g_proj[n][l][r] = sum_{m=0}^{511} x[n][m][l] * hh[r - m + 511]
// 256 threads, tile 128 l x 128 r, micro-tile 8l x 8r, packed fma.rn.f32x2.
// A-tile staging double-buffered via cp.async (FMA-pipe-bound kernel: the
// prefetch only hides L2 latency and doesn't contend meaningfully).
// ---------------------------------------------------------------------------
__global__ __launch_bounds__(256) void k_filter(const float* __restrict__ x) {
    __shared__ __align__(16) float2 hh2[1023];  // hh2[i] = (hh[i], hh[i+1])
    __shared__ __align__(16) float  As[2][16][128];
    const int tid = threadIdx.x;
    const int n     = blockIdx.z;
    const int rBase = blockIdx.x * 128;
    const int lBase = blockIdx.y * 128;

    for (int i = tid; i < 1023; i += 256)
        hh2[i] = make_float2(g_hh[i], g_hh[i + 1]);

    const int tx = tid & 15;          // l lane (strided by 16)
    const int ty = tid >> 4;          // r group (8 consecutive r)
    const int r0 = rBase + ty * 8;

    unsigned long long acc[8][4];     // [sl][pair]: pair p = (r0+2p, r0+2p+1)
#pragma unroll
    for (int sl = 0; sl < 8; ++sl)
#pragma unroll
        for (int p = 0; p < 4; ++p) acc[sl][p] = 0ull;

    const float* xn = x + (size_t)n * W * W;
    const int lrow = tid >> 5;        // 0..7
    const int c4   = (tid & 31) << 2; // 0..124
    const unsigned asb = (unsigned)__cvta_generic_to_shared(&As[0][0][0])
                       + (unsigned)(lrow * 128 + c4) * 4u;

    // stage chunk mc's 16x128 A-tile into buffer mc&1 (2 x 16B per thread)
#define ISSUEF(mc_)                                                         \
    do {                                                                    \
        const int _mc = (mc_);                                              \
        const float* _src = xn + (size_t)(_mc * 16) * W + lBase;            \
        unsigned _d = asb + (unsigned)(_mc & 1) * 8192u;                    \
        asm volatile("cp.async.cg.shared.global [%0], [%1], 16;"            \
                     :: "r"(_d), "l"(_src + (size_t)lrow * W + c4));        \
        asm volatile("cp.async.cg.shared.global [%0], [%1], 16;"            \
                     :: "r"(_d + 4096u),                                    \
                        "l"(_src + (size_t)(lrow + 8) * W + c4));           \
        asm volatile("cp.async.commit_group;");                             \
    } while (0)

    ISSUEF(0);

    for (int mc = 0; mc < 32; ++mc) {
        asm volatile("cp.async.wait_group 0;");
        __syncthreads();
        if (mc + 1 < 32) ISSUEF(mc + 1);   // buffer (mc+1)&1: all warps proved
                                           // done with chunk mc-1 by barrier
        const float (*A)[128] = As[mc & 1];
#pragma unroll
        for (int mm = 0; mm < 16; ++mm) {
            const int hb = 511 + r0 - (mc * 16 + mm);
            unsigned long long h2[4];
#pragma unroll
            for (int p = 0; p < 4; ++p)
                h2[p] = *(const unsigned long long*)(&hh2[hb + 2 * p]);
#pragma unroll
            for (int sl = 0; sl < 8; ++sl) {
                float a = A[mm][tx + 16 * sl];
                unsigned long long a2;
                asm("mov.b64 %0, {%1, %1};" : "=l"(a2) : "r"(__float_as_uint(a)));
#pragma unroll
                for (int p = 0; p < 4; ++p)
                    asm("fma.rn.f32x2 %0, %1, %2, %0;"
                        : "+l"(acc[sl][p]) : "l"(a2), "l"(h2[p]));
            }
        }
    }
#undef ISSUEF

#pragma unroll
    for (int sl = 0; sl < 8; ++sl) {
        const int l = lBase + tx + 16 * sl;
        float v[8];
#pragma unroll
        for (int p = 0; p < 4; ++p) {
            unsigned int lo, hi;
            asm("mov.b64 {%0, %1}, %2;" : "=r"(lo), "=r"(hi) : "l"(acc[sl][p]));
            v[2 * p]     = __uint_as_float(lo);
            v[2 * p + 1] = __uint_as_float(hi);
        }
        float* dst = g_proj + ((size_t)n * W + l) * W + r0;
        *(float4*)dst       = make_float4(v[0], v[1], v[2], v[3]);
        *(float4*)(dst + 4) = make_float4(v[4], v[5], v[6], v[7]);
    }
}

// pack two fp32 into half2 (lo in low half, hi in high half): 1 instr (F2FP)
__device__ __forceinline__ unsigned pack_f16x2(float lo, float hi) {
    unsigned r;
    asm("cvt.rn.f16x2.f32 %0, %2, %1;" : "=r"(r) : "f"(lo), "f"(hi));
    return r;
}

__device__ __forceinline__ __half2 u2h2(unsigned v) {
    return *reinterpret_cast<__half2*>(&v);
}

// ---------------------------------------------------------------------------
// K1.5: build packed fp16 quad tables from g_proj for 8-image groups.
// Block = one (group g, angle l); thread strides k. Entry (16B) holds
// p/d pairs for 4 images so K2 fetches them with one LDS.128.
// Index: ((g*512 + l)*2 + tab)*512 + k  ->  each (g, 4-angle chunk) is one
// contiguous 64KB block for the bulk copy in K2.
// ---------------------------------------------------------------------------
__global__ __launch_bounds__(128) void k_pack() {
    const int bid = blockIdx.x;            // g*512 + l
    const int g = bid >> 9;
    const int l = bid & 511;
    const int t = threadIdx.x;
    const float* base = g_proj + ((size_t)g * 8) * W * W + (size_t)l * W;
#pragma unroll
    for (int s = 0; s < 4; ++s) {
        int k  = t + s * 128;
        int kn = (k < W - 1) ? (k + 1) : k;      // k=511 -> d=0
        float p[8], d[8];
#pragma unroll
        for (int m = 0; m < 8; ++m) {
            p[m] = base[k  + (size_t)m * W * W];
            d[m] = base[kn + (size_t)m * W * W] - p[m];
        }
#pragma unroll
        for (int tab = 0; tab < 2; ++tab) {
            int m0 = tab * 4;
            g_pairs[(((size_t)bid * 2) + tab) * 512 + k] =
                make_uint4(pack_f16x2(p[m0 + 0], p[m0 + 1]),
                           pack_f16x2(d[m0 + 0], d[m0 + 1]),
                           pack_f16x2(p[m0 + 2], p[m0 + 3]),
                           pack_f16x2(d[m0 + 2], d[m0 + 3]));
        }
    }
}

// ---------------------------------------------------------------------------
// K2: backprojection, 8 images per block, triple-buffered BULK-COPY pipeline.
// Chunk tables (64KB) arrive via single-thread cp.async.bulk + mbarrier —
// zero LDGSTS in the warps' instruction streams, so the LSU dispatch queue
// carries only compute LDS (the R15/R16 regressions showed LDGSTS bursts
// queueing ahead of compute LDS). Compute is bit-identical to R14:
// angle PAIRS in fp16 (LDS.128 quad -> 2x HFMA2/tab), HADD2 merge, fp32
// flush per pair. Index via 2^23 magic; "& 0x1FF" wraps out-of-circle
// garbage in-bounds (masked at the end).
// ---------------------------------------------------------------------------
__global__ __launch_bounds__(512, 1) void k_backproj(float* __restrict__ out) {
    extern __shared__ __align__(16) char sm[];   // NBUF * CHUNK_BYTES
    __shared__ __align__(8) unsigned long long s_mbar[NBUF];
    const int tid  = threadIdx.x;
    const int rg   = blockIdx.x >> 1;       // row group (0..31)
    const int chh  = blockIdx.x & 1;        // column half
    const int n0   = blockIdx.y * 8;
    const int i    = rg * 16 + (tid >> 5);
    const int lane = tid & 31;
    const float STEP = 2.0f / 511.0f;
    const float ti   = fmaf((float)i, STEP, -1.0f);
    const float tj0  = fmaf((float)(chh * 256 + lane), STEP, -1.0f);
    const float UST0 = 32.0f * STEP;

    const char* gp = (const char*)g_pairs + (size_t)blockIdx.y * CHUNKS * CHUNK_BYTES;
    const unsigned smbase = (unsigned)__cvta_generic_to_shared(sm);
    const unsigned mbbase = (unsigned)__cvta_generic_to_shared(&s_mbar[0]);

    if (tid == 0) {
#pragma unroll
        for (int b = 0; b < NBUF; ++b)
            asm volatile("mbarrier.init.shared.b64 [%0], 1;"
                         :: "r"(mbbase + b * 8) : "memory");
    }
    __syncthreads();

    // single-thread 64KB bulk copy of chunk lc into buffer lc%NBUF
#define BISSUE(lc_)                                                          \
    do {                                                                     \
        const int _lc = (lc_);                                               \
        const unsigned _mb = mbbase + (unsigned)(_lc % NBUF) * 8u;           \
        const unsigned _dst = smbase + (unsigned)(_lc % NBUF) * CHUNK_BYTES; \
        const char* _src = gp + (size_t)_lc * CHUNK_BYTES;                   \
        asm volatile("mbarrier.arrive.expect_tx.shared.b64 _, [%0], %1;"     \
                     :: "r"(_mb), "r"((unsigned)CHUNK_BYTES) : "memory");    \
        asm volatile("cp.async.bulk.shared::cluster.global"                  \
                     ".mbarrier::complete_tx::bytes [%0], [%1], %2, [%3];"   \
                     :: "r"(_dst), "l"(_src), "r"((unsigned)CHUNK_BYTES),    \
                        "r"(_mb) : "memory");                                \
    } while (0)

    if (tid == 0) { BISSUE(0); BISSUE(1); }

    float acc[8][8];                         // [image][u]
#pragma unroll
    for (int m = 0; m < 8; ++m)
#pragma unroll
        for (int u = 0; u < 8; ++u) acc[m][u] = 0.0f;

    for (int lc = 0; lc < CHUNKS; ++lc) {
        // wait for chunk lc's buffer (phase = (lc/NBUF)&1), acquire semantics
        {
            unsigned mb = mbbase + (unsigned)(lc % NBUF) * 8u;
            unsigned ph = (unsigned)(lc / NBUF) & 1u;
            unsigned done;
            asm volatile(
                "{\n\t.reg .pred p;\n\t"
                "mbarrier.try_wait.parity.acquire.cta.shared::cta.b64 p, [%1], %2;\n\t"
                "selp.b32 %0, 1, 0, p;\n\t}"
                : "=r"(done) : "r"(mb), "r"(ph) : "memory");
            if (!done) {
                asm volatile(
                    "{\n\t.reg .pred P1;\n\t"
                    "WL_%=:\n\t"
                    "mbarrier.try_wait.parity.acquire.cta.shared::cta.b64 P1, [%0], %1, 0x989680;\n\t"
                    "@P1 bra.uni WD_%=;\n\t"
                    "bra.uni WL_%=;\n\t"
                    "WD_%=:\n\t}"
                    :: "r"(mb), "r"(ph) : "memory");
            }
        }
        __syncthreads();   // all threads past chunk lc-1 -> buffer (lc+2)%3 reusable
        if (tid == 0 && lc + 2 < CHUNKS) BISSUE(lc + 2);

        const char* cbase = sm + (lc % NBUF) * CHUNK_BYTES;
        const float4 csA = *(const float4*)&g_cs[lc * CH];      // c0,s0,c1,s1
        const float4 csB = *(const float4*)&g_cs[lc * CH + 2];  // c2,s2,c3,s3

#pragma unroll
        for (int ap = 0; ap < 2; ++ap) {      // angle pair (2*ap, 2*ap+1)
            const float cE = (ap == 0) ? csA.x : csB.x;
            const float sE = (ap == 0) ? csA.y : csB.y;
            const float cO = (ap == 0) ? csA.z : csB.z;
            const float sO = (ap == 0) ? csA.w : csB.w;
            const float rowE = fmaf(-ti, sE, 255.5f);
            const float rowO = fmaf(-ti, sO, 255.5f);
            const float ry0E = fmaf(tj0, cE, rowE);
            const float ry0O = fmaf(tj0, cO, rowO);
            const float ustE = cE * UST0;
            const float ustO = cO * UST0;
            const char* PE = cbase + (2 * ap)     * 16384;  // tab0; tab1 at +8192
            const char* PO = cbase + (2 * ap + 1) * 16384;
#pragma unroll
            for (int u = 0; u < 8; ++u) {
                // even angle
                float ryE = fmaf((float)u, ustE, ry0E);
                float bE;
                asm("add.rm.f32 %0, %1, 0f4B000000;" : "=f"(bE) : "f"(ryE));
                unsigned offE = (__float_as_uint(bE) & 0x1FFu) * 16u;
                float frE = ryE - (bE - 8388608.0f);
                __half2 hfE = u2h2(pack_f16x2(frE, frE));
                uint4 ea = *(const uint4*)(PE + offE);
                uint4 eb = *(const uint4*)(PE + 8192 + offE);
                __half2 e0 = __hfma2(hfE, u2h2(ea.y), u2h2(ea.x));
                __half2 e1 = __hfma2(hfE, u2h2(ea.w), u2h2(ea.z));
                __half2 e2 = __hfma2(hfE, u2h2(eb.y), u2h2(eb.x));
                __half2 e3 = __hfma2(hfE, u2h2(eb.w), u2h2(eb.z));
                // odd angle
                float ryO = fmaf((float)u, ustO, ry0O);
                float bO;
                asm("add.rm.f32 %0, %1, 0f4B000000;" : "=f"(bO) : "f"(ryO));
                unsigned offO = (__float_as_uint(bO) & 0x1FFu) * 16u;
                float frO = ryO - (bO - 8388608.0f);
                __half2 hfO = u2h2(pack_f16x2(frO, frO));
                uint4 oa = *(const uint4*)(PO + offO);
                uint4 ob = *(const uint4*)(PO + 8192 + offO);
                __half2 m0 = __hadd2(e0, __hfma2(hfO, u2h2(oa.y), u2h2(oa.x)));
                __half2 m1 = __hadd2(e1, __hfma2(hfO, u2h2(oa.w), u2h2(oa.z)));
                __half2 m2 = __hadd2(e2, __hfma2(hfO, u2h2(ob.y), u2h2(ob.x)));
                __half2 m3 = __hadd2(e3, __hfma2(hfO, u2h2(ob.w), u2h2(ob.z)));
                acc[0][u] += __low2float(m0);  acc[1][u] += __high2float(m0);
                acc[2][u] += __low2float(m1);  acc[3][u] += __high2float(m1);
                acc[4][u] += __low2float(m2);  acc[5][u] += __high2float(m2);
                acc[6][u] += __low2float(m3);  acc[7][u] += __high2float(m3);
            }
        }
    }
#undef BISSUE

    const float scale = (float)(3.14159265358979323846 / 1024.0); // pi/(2L)
    const float ti2 = ti * ti;
#pragma unroll
    for (int u = 0; u < 8; ++u) {
        int j = chh * 256 + lane + 32 * u;
        float tj = fmaf((float)j, STEP, -1.0f);
        bool in = (ti2 + tj * tj <= 1.0f);
        float* po = out + ((size_t)n0 * W + i) * W + j;
#pragma unroll
        for (int m = 0; m < 8; ++m)
            po[(size_t)m * W * W] = in ? acc[m][u] * scale : 0.0f;
    }
}

extern "C" void kernel_launch(void* const* d_in, const int* in_sizes, int n_in,
                              void* d_out, int out_size) {
    const float* x     = (const float*)d_in[0];
    const float* theta = (const float*)d_in[1];
    if (n_in >= 2 && in_sizes[0] == W && in_sizes[1] != W) { // defensive order swap
        x = (const float*)d_in[1];
        theta = (const float*)d_in[0];
    }
    float* out = (float*)d_out;

    const int smbytes = NBUF * CHUNK_BYTES;   // 192 KB dynamic smem
    cudaFuncSetAttribute(k_backproj, cudaFuncAttributeMaxDynamicSharedMemorySize,
                         smbytes);

    k_hh<<<1024, 256>>>();
    k_trig<<<1, 512>>>(theta);

    dim3 g1(4, 4, NIMG);
    k_filter<<<g1, 256>>>(x);

    k_pack<<<NGRP * W, 128>>>();

    dim3 g2(64, NGRP);
    k_backproj<<<g2, 512, smbytes>>>(out);
}